// round 5
// baseline (speedup 1.0000x reference)
#include <cuda_runtime.h>
#include <cuda_bf16.h>

// x: [1, 16, 64, 96, 96] fp32
#define Cn   16
#define Dn   64
#define Hn   96
#define Wn   96
#define HWn  (Hn*Wn)
#define VOLn (Dn*HWn)
#define KSEL 8

// lane = w (region 32, interior [2,30)), NW warps x 2 rows = 36-row region
#define RW     32
#define TWI    28
#define NW     18
#define HPT    2
#define RH     (NW*HPT)      // 36 region rows, interior [2,34) -> 32 rows
#define DCHUNK 16
#define NSTEP  (DCHUNK+2)    // 18 steps, divisible by 3 for register ring
#define DOFF   32            // packed pair: depth d and d+32

__device__ float d_partial[32][3][4];     // [z=c*2+pair][by][bx]
__device__ int   d_topidx[KSEL];

typedef unsigned long long u64;

__device__ __forceinline__ u64 pk(float lo, float hi) {
    u64 d; asm("mov.b64 %0,{%1,%2};" : "=l"(d) : "f"(lo), "f"(hi)); return d;
}
__device__ __forceinline__ void upk(u64 v, float& lo, float& hi) {
    asm("mov.b64 {%0,%1},%2;" : "=f"(lo), "=f"(hi) : "l"(v));
}
__device__ __forceinline__ u64 padd(u64 a, u64 b) {
    u64 d; asm("add.rn.f32x2 %0,%1,%2;" : "=l"(d) : "l"(a), "l"(b)); return d;
}
__device__ __forceinline__ u64 pmul(u64 a, u64 b) {
    u64 d; asm("mul.rn.f32x2 %0,%1,%2;" : "=l"(d) : "l"(a), "l"(b)); return d;
}
__device__ __forceinline__ u64 pfma(u64 a, u64 b, u64 c) {
    u64 d; asm("fma.rn.f32x2 %0,%1,%2,%3;" : "=l"(d) : "l"(a), "l"(b), "l"(c)); return d;
}
__device__ __forceinline__ u64 shfl64(u64 v, int src) {
    float lo, hi; upk(v, lo, hi);
    lo = __shfl_sync(0xffffffffu, lo, src & 31);
    hi = __shfl_sync(0xffffffffu, hi, src & 31);
    return pk(lo, hi);
}

extern __shared__ u64 dynsmem[];

__global__ __launch_bounds__(RW*NW, 1)
void harris_kernel(const float* __restrict__ x) {
    u64*  su  = dynsmem;                         // [3][RH+2][RW]  u1,u2,u3
    u64*  sq  = su + 3*(RH+2)*RW;                // [6][RH+2][RW]  w-boxed products
    float* red = (float*)(sq + 6*(RH+2)*RW);     // [NW]

    const int lane = threadIdx.x;
    const int wy   = threadIdx.y;
    const int R0   = wy * HPT;
    const int w0   = blockIdx.x * TWI;           // 0,28,56,84
    const int h0   = blockIdx.y * (RH - 4);      // 0,32,64
    const int c    = blockIdx.z >> 1;
    const int e0   = (blockIdx.z & 1) * DCHUNK;  // lo chunk: e0, hi chunk: e0+32
    const int w    = w0 + lane - 2;

    // zero pad rows (row index = region_row + 1; pads feed only masked outputs)
    if (wy == 0) {
        #pragma unroll
        for (int k = 0; k < 3; k++) su[(k*(RH+2) + 0)*RW + lane] = 0ull;
        #pragma unroll
        for (int k = 0; k < 6; k++) sq[(k*(RH+2) + 0)*RW + lane] = 0ull;
    }
    if (wy == NW-1) {
        #pragma unroll
        for (int k = 0; k < 3; k++) su[(k*(RH+2) + RH+1)*RW + lane] = 0ull;
        #pragma unroll
        for (int k = 0; k < 6; k++) sq[(k*(RH+2) + RH+1)*RW + lane] = 0ull;
    }

    bool hwok[HPT];
    int  hoff[HPT];
    u64  vmk[HPT];
    #pragma unroll
    for (int r = 0; r < HPT; r++) {
        int Rr = R0 + r;
        int h  = h0 + Rr - 2;
        hwok[r] = (h >= 0 && h < Hn && w >= 0 && w < Wn);
        hoff[r] = h * Wn + w;
        bool vm = (Rr >= 2 && Rr < RH-2) && (lane >= 2 && lane < RW-2) && (w < Wn);
        vmk[r]  = vm ? pk(1.f, 1.f) : 0ull;
    }

    const u64 NEG1 = pk(-1.f, -1.f);
    const u64 TWOp = pk(2.f, 2.f);
    const u64 C1p  = pk(1.f/19683.f, 1.f/19683.f);
    const u64 NC2p = pk(-0.04f/729.f, -0.04f/729.f);
    auto psub = [&](u64 a, u64 b) { return pfma(b, NEG1, a); };

    const float* __restrict__ xch = x + (size_t)c * VOLn;
    // packed load: (x at depth d, x at depth d+32), zero outside volume
    auto loadx2 = [&](int d, int r) -> u64 {
        float lo = 0.f, hi = 0.f;
        if (hwok[r]) {
            if (d >= 0)        lo = __ldg(xch + (size_t)d          * HWn + hoff[r]);
            if (d + DOFF < Dn) hi = __ldg(xch + (size_t)(d + DOFF) * HWn + hoff[r]);
        }
        return pk(lo, hi);
    };

    // d-direction running box ring, packed over (chunk, chunk+32)
    u64 Ss[6][HPT], Rl[6][HPT];
    #pragma unroll
    for (int k = 0; k < 6; k++)
        #pragma unroll
        for (int r = 0; r < HPT; r++) { Ss[k][r] = 0ull; Rl[k][r] = 0ull; }
    u64 accp[HPT] = {0ull, 0ull};

    u64 xa[HPT], xb[HPT], xc[HPT];
    #pragma unroll
    for (int r = 0; r < HPT; r++) { xa[r] = loadx2(e0-2, r); xb[r] = loadx2(e0-1, r); xc[r] = loadx2(e0, r); }

    // one step at plane f (lo) / f+32 (hi): builds hw-boxed products, emits e=f-1
    auto step = [&](int f, u64 (&XA)[HPT], u64 (&XB)[HPT], u64 (&XC)[HPT]) {
        // s = Sd111(x), t = Dd(x)
        u64 s0 = padd(padd(XA[0], XB[0]), XC[0]);
        u64 s1 = padd(padd(XA[1], XB[1]), XC[1]);
        u64 t0 = psub(XC[0], XA[0]);
        u64 t1 = psub(XC[1], XA[1]);
        // prefetch plane f+2 into the retiring slot (hidden across this step)
        XA[0] = loadx2(f + 2, 0);
        XA[1] = loadx2(f + 2, 1);

        u64 sl0 = shfl64(s0, lane-1), sr0 = shfl64(s0, lane+1);
        u64 sl1 = shfl64(s1, lane-1), sr1 = shfl64(s1, lane+1);
        u64 tl0 = shfl64(t0, lane-1), tr0 = shfl64(t0, lane+1);
        u64 tl1 = shfl64(t1, lane-1), tr1 = shfl64(t1, lane+1);

        u64 u1_0 = psub(sr0, sl0),               u1_1 = psub(sr1, sl1);              // Dw(s)
        u64 u2_0 = pfma(s0, TWOp, padd(sl0,sr0)), u2_1 = pfma(s1, TWOp, padd(sl1,sr1)); // Sw121(s)
        u64 u3_0 = padd(padd(tl0, t0), tr0),     u3_1 = padd(padd(tl1, t1), tr1);    // Sw111(t)

        su[(0*(RH+2) + R0+1)*RW + lane] = u1_0;  su[(0*(RH+2) + R0+2)*RW + lane] = u1_1;
        su[(1*(RH+2) + R0+1)*RW + lane] = u2_0;  su[(1*(RH+2) + R0+2)*RW + lane] = u2_1;
        su[(2*(RH+2) + R0+1)*RW + lane] = u3_0;  su[(2*(RH+2) + R0+2)*RW + lane] = u3_1;
        __syncthreads();

        const bool okl = (f >= 0);                // f < Dn always here
        const bool okh = (f + DOFF < Dn);
        #pragma unroll
        for (int r = 0; r < HPT; r++) {
            u64 a1, b1, a2, b2, a3, b3;
            if (r == 0) {
                a1 = su[(0*(RH+2) + R0)*RW + lane];  b1 = u1_1;
                a2 = su[(1*(RH+2) + R0)*RW + lane];  b2 = u2_1;
                a3 = su[(2*(RH+2) + R0)*RW + lane];  b3 = u3_1;
            } else {
                a1 = u1_0;  b1 = su[(0*(RH+2) + R0+3)*RW + lane];
                a2 = u2_0;  b2 = su[(1*(RH+2) + R0+3)*RW + lane];
                a3 = u3_0;  b3 = su[(2*(RH+2) + R0+3)*RW + lane];
            }
            u64 uc1 = (r == 0) ? u1_0 : u1_1;
            u64 uc3 = (r == 0) ? u3_0 : u3_1;
            u64 gx = pfma(uc1, TWOp, padd(a1, b1));   // Sh121(Dw(s))
            u64 gy = psub(b2, a2);                    // Dh(Sw121(s))
            u64 gz = padd(padd(a3, uc3), b3);         // Sh111(Sw111(t))
            // zero products outside volume (box zero-padding)
            u64 mg = pk((okl && hwok[r]) ? 1.f : 0.f, (okh && hwok[r]) ? 1.f : 0.f);
            gx = pmul(gx, mg); gy = pmul(gy, mg); gz = pmul(gz, mg);

            u64 p0 = pmul(gx,gx), p1 = pmul(gy,gy), p2 = pmul(gz,gz);
            u64 p3 = pmul(gx,gy), p4 = pmul(gx,gz), p5 = pmul(gy,gz);
            u64 pp[6] = { p0, p1, p2, p3, p4, p5 };
            #pragma unroll
            for (int k = 0; k < 6; k++) {
                u64 pl = shfl64(pp[k], lane-1);
                u64 pr = shfl64(pp[k], lane+1);
                sq[(k*(RH+2) + R0+1+r)*RW + lane] = padd(padd(pl, pp[k]), pr); // Sw111
            }
        }
        __syncthreads();

        const bool emit = (f > e0);
        #pragma unroll
        for (int r = 0; r < HPT; r++) {
            u64 Cv[6];
            #pragma unroll
            for (int k = 0; k < 6; k++) {
                const u64* Q = sq + (k*(RH+2) + R0 + r)*RW + lane;  // rows Rr-1,Rr,Rr+1
                u64 qc = padd(padd(Q[0], Q[RW]), Q[2*RW]);          // Sh111 -> q(f)
                Cv[k]    = padd(Ss[k][r], qc);   // q(f-2)+q(f-1)+q(f) = 27*B(f-1)
                Ss[k][r] = padd(Rl[k][r], qc);
                Rl[k][r] = qc;
            }
            u64 m1 = psub(pmul(Cv[1],Cv[2]), pmul(Cv[5],Cv[5]));
            u64 m2 = psub(pmul(Cv[3],Cv[2]), pmul(Cv[5],Cv[4]));
            u64 m3 = psub(pmul(Cv[3],Cv[5]), pmul(Cv[1],Cv[4]));
            u64 det = pmul(Cv[0], m1);
            det = psub(det, pmul(Cv[3], m2));
            det = pfma(Cv[4], m3, det);
            u64 tr = padd(padd(Cv[0], Cv[1]), Cv[2]);
            u64 hv = pfma(pmul(tr, tr), NC2p, pmul(det, C1p));
            if (emit) accp[r] = pfma(hv, vmk[r], accp[r]);   // finite everywhere: safe
        }
    };

    int fb = e0 - 1;
    #pragma unroll 1
    for (int it = 0; it < NSTEP; it += 3) {
        step(fb,   xa, xb, xc);
        step(fb+1, xb, xc, xa);
        step(fb+2, xc, xa, xb);
        fb += 3;
    }

    // reduce block -> deterministic per-block partial
    float a0, a1, b0, b1;
    upk(accp[0], a0, a1); upk(accp[1], b0, b1);
    float acc = (a0 + a1) + (b0 + b1);
    #pragma unroll
    for (int o = 16; o > 0; o >>= 1)
        acc += __shfl_down_sync(0xffffffffu, acc, o);
    if (lane == 0) red[wy] = acc;
    __syncthreads();
    if (wy == 0) {
        float v = (lane < NW) ? red[lane] : 0.f;
        #pragma unroll
        for (int o = 16; o > 0; o >>= 1)
            v += __shfl_down_sync(0xffffffffu, v, o);
        if (lane == 0) d_partial[blockIdx.z][blockIdx.y][blockIdx.x] = v;
    }
}

// top-8, strict > selection: lowest index wins ties (matches lax.top_k)
__global__ void topk_kernel() {
    if (threadIdx.x == 0 && blockIdx.x == 0) {
        float p[Cn];
        for (int i = 0; i < Cn; i++) {
            float s = 0.f;
            for (int pr = 0; pr < 2; pr++)
                for (int y = 0; y < 3; y++)
                    for (int xx = 0; xx < 4; xx++)
                        s += d_partial[i*2 + pr][y][xx];
            p[i] = s;
        }
        bool used[Cn];
        for (int i = 0; i < Cn; i++) used[i] = false;
        for (int j = 0; j < KSEL; j++) {
            int best = -1; float bv = 0.f;
            for (int i = 0; i < Cn; i++) {
                if (used[i]) continue;
                if (best < 0 || p[i] > bv) { best = i; bv = p[i]; }
            }
            used[best] = true;
            d_topidx[j] = best;
        }
    }
}

__global__ void gather_kernel(const float* __restrict__ x, float* __restrict__ out) {
    const int per    = VOLn / 4;     // float4 per channel = 147456
    const int groups = per / 4;      // 4 float4 per thread
    int j = blockIdx.x * blockDim.x + threadIdx.x;
    if (j >= KSEL * groups) return;
    int ch  = j / groups;
    int off = (j - ch * groups) * 4;
    int src = d_topidx[ch];
    const float4* s = (const float4*)(x + (size_t)src * VOLn);
    float4* o = (float4*)out + (size_t)ch * per;
    float4 v0 = s[off], v1 = s[off+1], v2 = s[off+2], v3 = s[off+3];
    o[off] = v0; o[off+1] = v1; o[off+2] = v2; o[off+3] = v3;
}

extern "C" void kernel_launch(void* const* d_in, const int* in_sizes, int n_in,
                              void* d_out, int out_size) {
    const float* x = (const float*)d_in[0];   // Sobel weights fixed; hardcoded
    float* out = (float*)d_out;

    size_t smem_bytes = (3*(RH+2)*RW + 6*(RH+2)*RW) * sizeof(u64) + NW * sizeof(float);
    cudaFuncSetAttribute(harris_kernel,
                         cudaFuncAttributeMaxDynamicSharedMemorySize, (int)smem_bytes);

    dim3 grid(4, 3, 32);                      // 384 blocks, 4 voxels/thread/step
    harris_kernel<<<grid, dim3(RW, NW), smem_bytes>>>(x);
    topk_kernel<<<1, 1>>>();
    int nthreads = KSEL * (VOLn / 16);        // 294912
    gather_kernel<<<nthreads / 256, 256>>>(x, out);
}

// round 6
// speedup vs baseline: 1.2007x; 1.2007x over previous
#include <cuda_runtime.h>
#include <cuda_bf16.h>

// x: [1, 16, 64, 96, 96] fp32
#define Cn   16
#define Dn   64
#define Hn   96
#define Wn   96
#define HWn  (Hn*Wn)
#define VOLn (Dn*HWn)
#define KSEL 8

// lane covers w-pair (2*lane, 2*lane+1) in a 64-wide region, interior [2,50)
#define RW     32
#define NW     18
#define HPT    2
#define RH     (NW*HPT)      // 36 region rows, interior [2,34)
#define DCHUNK 16
#define NSTEP  (DCHUNK+2)    // 18, divisible by 3 for register ring

__device__ float d_partial[64][3][2];   // [z=c*4+chunk][by][bx]
__device__ int   d_topidx[KSEL];

typedef unsigned long long u64;

__device__ __forceinline__ u64 pk(float lo, float hi) {
    u64 d; asm("mov.b64 %0,{%1,%2};" : "=l"(d) : "f"(lo), "f"(hi)); return d;
}
__device__ __forceinline__ void upk(u64 v, float& lo, float& hi) {
    asm("mov.b64 {%0,%1},%2;" : "=f"(lo), "=f"(hi) : "l"(v));
}
__device__ __forceinline__ u64 padd(u64 a, u64 b) {
    u64 d; asm("add.rn.f32x2 %0,%1,%2;" : "=l"(d) : "l"(a), "l"(b)); return d;
}
__device__ __forceinline__ u64 pmul(u64 a, u64 b) {
    u64 d; asm("mul.rn.f32x2 %0,%1,%2;" : "=l"(d) : "l"(a), "l"(b)); return d;
}
__device__ __forceinline__ u64 pfma(u64 a, u64 b, u64 c) {
    u64 d; asm("fma.rn.f32x2 %0,%1,%2,%3;" : "=l"(d) : "l"(a), "l"(b), "l"(c)); return d;
}
__device__ __forceinline__ float shfl(float v, int src) {
    return __shfl_sync(0xffffffffu, v, src & 31);
}
// value pair at (w-1, w): one SHFL + repack
__device__ __forceinline__ u64 shiftL(u64 v, int lane) {
    float lo, hi; upk(v, lo, hi);
    return pk(shfl(hi, lane - 1), lo);
}
// value pair at (w+1, w+2)
__device__ __forceinline__ u64 shiftR(u64 v, int lane) {
    float lo, hi; upk(v, lo, hi);
    return pk(hi, shfl(lo, lane + 1));
}

extern __shared__ u64 dynsmem[];

__global__ __launch_bounds__(RW*NW, 1)
void harris_kernel(const float* __restrict__ x) {
    u64*  su  = dynsmem;                      // [3][RH+2][RW] u1,u2,u3 (u64 = w-pair)
    u64*  sq  = su + 3*(RH+2)*RW;             // [6][RH+2][RW] w-boxed products
    float* red = (float*)(sq + 6*(RH+2)*RW);  // [NW]

    const int lane = threadIdx.x;
    const int wy   = threadIdx.y;
    const int R0   = wy * HPT;
    const int bx   = blockIdx.x;              // 0,1 -> emit w windows [0,48),[48,96)
    const int h0   = blockIdx.y * 32;         // 0,32,64
    const int c    = blockIdx.z >> 2;
    const int e0   = (blockIdx.z & 3) * DCHUNK;
    const int wlo  = bx * 48 - 2 + 2 * lane;  // even

    // zero pad rows (read only by masked outputs; must be finite)
    if (wy == 0) {
        #pragma unroll
        for (int k = 0; k < 3; k++) su[(k*(RH+2))*RW + lane] = 0ull;
        #pragma unroll
        for (int k = 0; k < 6; k++) sq[(k*(RH+2))*RW + lane] = 0ull;
    }
    if (wy == NW-1) {
        #pragma unroll
        for (int k = 0; k < 3; k++) su[(k*(RH+2) + RH+1)*RW + lane] = 0ull;
        #pragma unroll
        for (int k = 0; k < 6; k++) sq[(k*(RH+2) + RH+1)*RW + lane] = 0ull;
    }

    bool hwok[HPT];
    int  hoff[HPT];
    u64  vmk[HPT];
    #pragma unroll
    for (int r = 0; r < HPT; r++) {
        int Rr = R0 + r;
        int h  = h0 + Rr - 2;
        hwok[r] = (h >= 0 && h < Hn) && (wlo >= 0 && wlo < Wn);  // pair all-in/all-out
        hoff[r] = h * Wn + wlo;
        bool vm = (lane >= 1 && lane <= 24) && (Rr >= 2 && Rr < RH-2);
        vmk[r]  = vm ? pk(1.f, 1.f) : 0ull;
    }

    const u64 NEG1 = pk(-1.f, -1.f);
    const u64 TWOp = pk(2.f, 2.f);
    const u64 PONE = pk(1.f, 1.f);
    const u64 C1p  = pk(1.f/19683.f, 1.f/19683.f);
    const u64 NC2p = pk(-0.04f/729.f, -0.04f/729.f);
    auto psub = [&](u64 a, u64 b) { return pfma(b, NEG1, a); };

    const float* __restrict__ xch = x + (size_t)c * VOLn;
    auto loadx2 = [&](int d, int r) -> u64 {
        if (hwok[r] && d >= 0 && d < Dn) {
            float2 v = *(const float2*)(xch + (size_t)d * HWn + hoff[r]);
            return pk(v.x, v.y);
        }
        return 0ull;
    };

    u64 Ss[6][HPT], Rl[6][HPT];
    #pragma unroll
    for (int k = 0; k < 6; k++)
        #pragma unroll
        for (int r = 0; r < HPT; r++) { Ss[k][r] = 0ull; Rl[k][r] = 0ull; }
    u64 accp = 0ull;

    u64 xa[HPT], xb[HPT], xc[HPT];
    #pragma unroll
    for (int r = 0; r < HPT; r++) {
        xa[r] = loadx2(e0-2, r); xb[r] = loadx2(e0-1, r); xc[r] = loadx2(e0, r);
    }

    // step at plane f: builds hw-boxed products q(f), emits voxel depth e=f-1
    auto step = [&](int f, u64 (&XA)[HPT], u64 (&XB)[HPT], u64 (&XC)[HPT]) {
        u64 s[HPT], t[HPT];
        #pragma unroll
        for (int r = 0; r < HPT; r++) {
            s[r] = padd(padd(XA[r], XB[r]), XC[r]);   // Sd111(x)
            t[r] = psub(XC[r], XA[r]);                // Dd(x)
        }
        // prefetch plane f+2 into retiring slot
        XA[0] = loadx2(f + 2, 0);
        XA[1] = loadx2(f + 2, 1);

        u64 u1[HPT], u2[HPT], u3[HPT];
        #pragma unroll
        for (int r = 0; r < HPT; r++) {
            u64 sl = shiftL(s[r], lane), sr = shiftR(s[r], lane);
            u64 tl = shiftL(t[r], lane), tr = shiftR(t[r], lane);
            u1[r] = psub(sr, sl);                     // Dw(s)
            u2[r] = pfma(s[r], TWOp, padd(sl, sr));   // Sw121(s)
            u3[r] = padd(padd(tl, t[r]), tr);         // Sw111(t)
            su[(0*(RH+2) + R0+1+r)*RW + lane] = u1[r];
            su[(1*(RH+2) + R0+1+r)*RW + lane] = u2[r];
            su[(2*(RH+2) + R0+1+r)*RW + lane] = u3[r];
        }
        __syncthreads();

        const bool fok = (f >= 0 && f < Dn);
        u64 qw[HPT][6];
        #pragma unroll
        for (int r = 0; r < HPT; r++) {
            u64 u1m, u1p, u2m, u2p, u3m, u3p;
            if (r == 0) {
                u1m = su[(0*(RH+2) + R0)*RW + lane];  u1p = u1[1];
                u2m = su[(1*(RH+2) + R0)*RW + lane];  u2p = u2[1];
                u3m = su[(2*(RH+2) + R0)*RW + lane];  u3p = u3[1];
            } else {
                u1m = u1[0];  u1p = su[(0*(RH+2) + R0+3)*RW + lane];
                u2m = u2[0];  u2p = su[(1*(RH+2) + R0+3)*RW + lane];
                u3m = u3[0];  u3p = su[(2*(RH+2) + R0+3)*RW + lane];
            }
            u64 gx = pfma(u1[r], TWOp, padd(u1m, u1p));  // Sh121(Dw(s))
            u64 gy = psub(u2p, u2m);                     // Dh(Sw121(s))
            u64 gz = padd(padd(u3m, u3[r]), u3p);        // Sh111(Sw111(t))
            u64 mg = (fok && hwok[r]) ? PONE : 0ull;     // box zero-padding
            gx = pmul(gx, mg); gy = pmul(gy, mg); gz = pmul(gz, mg);

            u64 pp[6] = { pmul(gx,gx), pmul(gy,gy), pmul(gz,gz),
                          pmul(gx,gy), pmul(gx,gz), pmul(gy,gz) };
            #pragma unroll
            for (int k = 0; k < 6; k++) {
                u64 q = padd(padd(shiftL(pp[k], lane), pp[k]), shiftR(pp[k], lane));
                qw[r][k] = q;                            // Sw111 of products
                sq[(k*(RH+2) + R0+1+r)*RW + lane] = q;
            }
        }
        __syncthreads();

        const bool emit = (f > e0);
        #pragma unroll
        for (int r = 0; r < HPT; r++) {
            u64 Cv[6];
            #pragma unroll
            for (int k = 0; k < 6; k++) {
                u64 qm = (r == 0) ? sq[(k*(RH+2) + R0)*RW + lane]   : qw[0][k];
                u64 qp = (r == 1) ? sq[(k*(RH+2) + R0+3)*RW + lane] : qw[1][k];
                u64 qc = padd(padd(qm, qw[r][k]), qp);   // Sh111 -> q(f)
                Cv[k]    = padd(Ss[k][r], qc);           // 27*B(f-1)
                Ss[k][r] = padd(Rl[k][r], qc);
                Rl[k][r] = qc;
            }
            u64 m1 = psub(pmul(Cv[1],Cv[2]), pmul(Cv[5],Cv[5]));
            u64 m2 = psub(pmul(Cv[3],Cv[2]), pmul(Cv[5],Cv[4]));
            u64 m3 = psub(pmul(Cv[3],Cv[5]), pmul(Cv[1],Cv[4]));
            u64 det = pmul(Cv[0], m1);
            det = psub(det, pmul(Cv[3], m2));
            det = pfma(Cv[4], m3, det);
            u64 tr = padd(padd(Cv[0], Cv[1]), Cv[2]);
            u64 hv = pfma(pmul(tr, tr), NC2p, pmul(det, C1p));
            if (emit) accp = pfma(hv, vmk[r], accp);     // finite everywhere: safe
        }
    };

    int fb = e0 - 1;
    #pragma unroll 1
    for (int it = 0; it < NSTEP; it += 3) {
        step(fb,   xa, xb, xc);
        step(fb+1, xb, xc, xa);
        step(fb+2, xc, xa, xb);
        fb += 3;
    }

    // block reduce -> deterministic per-block partial
    float a0, a1; upk(accp, a0, a1);
    float acc = a0 + a1;
    #pragma unroll
    for (int o = 16; o > 0; o >>= 1)
        acc += __shfl_down_sync(0xffffffffu, acc, o);
    if (lane == 0) red[wy] = acc;
    __syncthreads();
    if (wy == 0) {
        float v = (lane < NW) ? red[lane] : 0.f;
        #pragma unroll
        for (int o = 16; o > 0; o >>= 1)
            v += __shfl_down_sync(0xffffffffu, v, o);
        if (lane == 0) d_partial[blockIdx.z][blockIdx.y][blockIdx.x] = v;
    }
}

// top-8, strict > selection: lowest index wins ties (matches lax.top_k)
__global__ void topk_kernel() {
    if (threadIdx.x == 0 && blockIdx.x == 0) {
        float p[Cn];
        for (int i = 0; i < Cn; i++) {
            float s = 0.f;
            for (int ck = 0; ck < 4; ck++)
                for (int y = 0; y < 3; y++)
                    for (int xx = 0; xx < 2; xx++)
                        s += d_partial[i*4 + ck][y][xx];
            p[i] = s;
        }
        bool used[Cn];
        for (int i = 0; i < Cn; i++) used[i] = false;
        for (int j = 0; j < KSEL; j++) {
            int best = -1; float bv = 0.f;
            for (int i = 0; i < Cn; i++) {
                if (used[i]) continue;
                if (best < 0 || p[i] > bv) { best = i; bv = p[i]; }
            }
            used[best] = true;
            d_topidx[j] = best;
        }
    }
}

__global__ void gather_kernel(const float* __restrict__ x, float* __restrict__ out) {
    const int per    = VOLn / 4;     // float4 per channel = 147456
    const int groups = per / 4;      // 4 float4 per thread
    int j = blockIdx.x * blockDim.x + threadIdx.x;
    if (j >= KSEL * groups) return;
    int ch  = j / groups;
    int off = (j - ch * groups) * 4;
    int src = d_topidx[ch];
    const float4* s = (const float4*)(x + (size_t)src * VOLn);
    float4* o = (float4*)out + (size_t)ch * per;
    float4 v0 = s[off], v1 = s[off+1], v2 = s[off+2], v3 = s[off+3];
    o[off] = v0; o[off+1] = v1; o[off+2] = v2; o[off+3] = v3;
}

extern "C" void kernel_launch(void* const* d_in, const int* in_sizes, int n_in,
                              void* d_out, int out_size) {
    const float* x = (const float*)d_in[0];   // Sobel weights fixed; hardcoded
    float* out = (float*)d_out;

    size_t smem_bytes = 9 * (RH+2) * RW * sizeof(u64) + NW * sizeof(float);
    cudaFuncSetAttribute(harris_kernel,
                         cudaFuncAttributeMaxDynamicSharedMemorySize, (int)smem_bytes);

    dim3 grid(2, 3, 64);                      // 384 blocks x 576 threads
    harris_kernel<<<grid, dim3(RW, NW), smem_bytes>>>(x);
    topk_kernel<<<1, 1>>>();
    int nthreads = KSEL * (VOLn / 16);        // 294912
    gather_kernel<<<nthreads / 256, 256>>>(x, out);
}